// round 11
// baseline (speedup 1.0000x reference)
#include <cuda_runtime.h>
#include <math.h>
#include <float.h>

// Problem constants (fixed by the dataset)
#define S_   7
#define B_   2
#define C_   80
#define NGT  32
#define BT_  8192
#define CELLF 90                    // B*5 + C
#define NCELLS (BT_ * S_ * S_)      // 401408
#define NBOX   (NCELLS * B_)        // 802816
#define NGTS   (BT_ * NGT)          // 262144

#define NTHR 128
#define NBLK 4096                   // 524288 threads = 2 per GT
#define NTOT (NBLK * NTHR)
#define NWARP (NTHR / 32)           // 4

// Per-block partial sums: [coord, obj, posconf_sq, cls, npos, noobj_all]
__device__ double g_part[NBLK][6];
__device__ unsigned int g_count = 0;

__device__ __forceinline__ float sigmoidf_(float x) {
    return 1.0f / (1.0f + __expf(-x));
}

__global__ void __launch_bounds__(NTHR, 10)
yolo_loss_split(const float* __restrict__ preds,
                const float* __restrict__ gt_boxes,
                const int* __restrict__ gt_labels,
                const unsigned char* __restrict__ gt_valid,
                float* __restrict__ out)
{
    const int tid  = threadIdx.x;
    const int lane = tid & 31;
    const int wid  = tid >> 5;
    const int tg   = blockIdx.x * NTHR + tid;   // global thread id
    const int gt   = tg >> 1;                   // GT index (2 threads per GT)
    const int half = tg & 1;                    // 0: box + classes 0..39, 1: classes 40..79
    const unsigned FULL = 0xffffffffu;

    float coord = 0.f, obj = 0.f, posconf = 0.f, clsl = 0.f, npos = 0.f, noobj = 0.f;

    // ===== Phase 2 conf loads hoisted (<=1 cell per thread) =====
    float pa = 0.f, pb = 0.f;
    const bool hasC = (tg < NCELLS);
    if (hasC) {
        pa = __ldg(preds + (size_t)tg * CELLF + 4);
        pb = __ldg(preds + (size_t)tg * CELLF + 9);
    }

    // ===== GT metadata (lanes 2k,2k+1 read the same addresses -> dedup'd) =====
    const float mval = (__ldg(gt_valid + gt) != 0) ? 1.0f : 0.0f;
    const float4 gb  = __ldg((const float4*)gt_boxes + gt);
    const int   label = __ldg(gt_labels + gt);

    const float x1 = gb.x, y1 = gb.y, x2 = gb.z, y2 = gb.w;
    const float cx = (x1 + x2) * 0.5f;
    const float cy = (y1 + y2) * 0.5f;
    const int gi = min(max((int)floorf(cx * (float)S_), 0), S_ - 1);
    const int gj = min(max((int)floorf(cy * (float)S_), 0), S_ - 1);

    const int  b       = gt >> 5;                      // gt / NGT
    const int  cellIdx = b * (S_ * S_) + gj * S_ + gi;
    const float* cell  = preds + (size_t)cellIdx * CELLF;
    const float2* c2   = (const float2*)cell;          // cell base is 8B-aligned (360B stride)

    // label-logit scalar gather (even lane only; overlaps everything)
    float cl = 0.f;
    if (half == 0) cl = __ldg(cell + 10 + label);

    // box floats (even lane only): float2 slots 0..4
    float bx[10];
    if (half == 0) {
        #pragma unroll
        for (int j = 0; j < 5; j++) {
            const float2 v = __ldg(c2 + j);
            bx[2*j] = v.x; bx[2*j+1] = v.y;
        }
    }

    // ===== my 40 class logits: float2 slots 5+20*half .. 24+20*half =====
    const float2* cc = c2 + 5 + 20 * half;
    float s0 = 0.f, s1 = 0.f, q0 = 0.f, q1 = 0.f;
    #pragma unroll
    for (int chunk = 0; chunk < 2; chunk++) {
        float2 v[10];
        #pragma unroll
        for (int i = 0; i < 10; i++) v[i] = __ldg(cc + chunk * 10 + i);
        #pragma unroll
        for (int i = 0; i < 10; i++) {
            const float ea = __expf(v[i].x);
            const float eb = __expf(v[i].y);
            s0 += ea; q0 += ea * ea;
            s1 += eb; q1 += eb * eb;
        }
    }
    float s  = s0 + s1;
    float sq = q0 + q1;
    // combine the two halves of the GT
    s  += __shfl_xor_sync(FULL, s,  1);
    sq += __shfl_xor_sync(FULL, sq, 1);

    // phase-2 math (loads have long arrived)
    if (hasC) {
        const float sa = sigmoidf_(pa), sb = sigmoidf_(pb);
        noobj = sa * sa + sb * sb;
    }

    // ===== even-lane tail: cls term + IoU + coord/obj =====
    if (half == 0) {
        const float el  = __expf(cl);
        const float inv = 1.0f / s;
        const float cls_term = sq * inv * inv - 2.0f * el * inv + 1.0f;

        const float w = fmaxf(x2 - x1, 1e-6f);
        const float h = fmaxf(y2 - y1, 1e-6f);
        const float area_g = (x2 - x1) * (y2 - y1);

        float iou[2], sxk[2], syk[2], twk[2], thk[2], tok[2];
        #pragma unroll
        for (int k = 0; k < 2; k++) {
            const float tx = bx[k*5+0], ty = bx[k*5+1];
            const float tw = bx[k*5+2], th = bx[k*5+3];
            const float sx = sigmoidf_(tx);
            const float sy = sigmoidf_(ty);
            const float pw = tw * tw, ph = th * th;
            const float px = (sx + (float)gi) * (1.0f / S_);
            const float py = (sy + (float)gj) * (1.0f / S_);
            const float px1 = px - 0.5f * pw, px2v = px + 0.5f * pw;
            const float py1 = py - 0.5f * ph, py2v = py + 0.5f * ph;
            const float iw = fmaxf(0.f, fminf(px2v, x2) - fmaxf(px1, x1));
            const float ih = fmaxf(0.f, fminf(py2v, y2) - fmaxf(py1, y1));
            const float inter = iw * ih;
            iou[k] = inter / (pw * ph + area_g - inter + 1e-6f);
            sxk[k] = sx; syk[k] = sy; twk[k] = tw; thk[k] = th; tok[k] = bx[k*5+4];
        }
        const int   best = (iou[1] > iou[0]) ? 1 : 0;
        const float iou_best = fmaxf(iou[0], iou[1]);

        const float so  = sigmoidf_(tok[best]);
        const float tgx = cx * (float)S_ - (float)gi;
        const float tgy = cy * (float)S_ - (float)gj;
        const float tgw = sqrtf(w), tgh = sqrtf(h);
        const float dx = sxk[best] - tgx, dy = syk[best] - tgy;
        const float dw = twk[best] - tgw, dh = thk[best] - tgh;
        const float dob = so - iou_best;

        coord   = mval * (dx*dx + dy*dy + dw*dw + dh*dh);
        obj     = mval * dob * dob;
        posconf = mval * so * so;
        npos    = mval;
        clsl    = mval * cls_term;
    }

    // ================= Block reduction -> g_part =================
    float vals[6] = {coord, obj, posconf, clsl, npos, noobj};
    #pragma unroll
    for (int j = 0; j < 6; j++) {
        #pragma unroll
        for (int o = 16; o; o >>= 1)
            vals[j] += __shfl_xor_sync(FULL, vals[j], o);
    }
    __shared__ double sh[NWARP][6];
    if (lane == 0) {
        #pragma unroll
        for (int j = 0; j < 6; j++) sh[wid][j] = (double)vals[j];
    }
    __syncthreads();
    if (tid < 6) {
        double acc = 0.0;
        #pragma unroll
        for (int wI = 0; wI < NWARP; wI++) acc += sh[wI][tid];
        g_part[blockIdx.x][tid] = acc;
    }

    // ================= Grid-wide finalize: last block reduces =================
    __shared__ bool is_last;
    __threadfence();
    if (tid == 0) {
        const unsigned prev = atomicAdd(&g_count, 1u);
        is_last = (prev == (unsigned)(NBLK - 1));
        if (is_last) g_count = 0u;          // reset for next graph replay
    }
    __syncthreads();
    if (!is_last) return;

    double a[6] = {0, 0, 0, 0, 0, 0};
    for (int bb = tid; bb < NBLK; bb += NTHR) {
        #pragma unroll
        for (int j = 0; j < 6; j++) a[j] += __ldcg(&g_part[bb][j]);
    }
    #pragma unroll
    for (int j = 0; j < 6; j++) {
        #pragma unroll
        for (int o = 16; o; o >>= 1)
            a[j] += __shfl_xor_sync(FULL, a[j], o);
    }
    __shared__ double shf[NWARP][6];
    if (lane == 0) {
        #pragma unroll
        for (int j = 0; j < 6; j++) shf[wid][j] = a[j];
    }
    __syncthreads();
    if (tid == 0) {
        double tt[6];
        #pragma unroll
        for (int j = 0; j < 6; j++) {
            tt[j] = 0.0;
            for (int wI = 0; wI < NWARP; wI++) tt[j] += shf[wI][j];
        }
        const double nposd = fmax(tt[4], 1.0);
        const double nneg  = fmax((double)NBOX - tt[4], 1.0);
        const double ncell = fmax(tt[4], 1.0);   // GT cells are distinct per batch item
        const double loss = 5.0 * tt[0] / nposd          // LC * coord
                          + tt[1] / nposd                // obj
                          + 0.5 * (tt[5] - tt[2]) / nneg // LN * noobj (all - positive)
                          + tt[3] / ncell;               // cls
        *out = (float)loss;
    }
}

extern "C" void kernel_launch(void* const* d_in, const int* in_sizes, int n_in,
                              void* d_out, int out_size)
{
    const float*         preds     = (const float*)d_in[0];
    const float*         gt_boxes  = (const float*)d_in[1];
    const int*           gt_labels = (const int*)d_in[2];
    const unsigned char* gt_valid  = (const unsigned char*)d_in[3];
    float* out = (float*)d_out;

    yolo_loss_split<<<NBLK, NTHR>>>(preds, gt_boxes, gt_labels, gt_valid, out);
}

// round 12
// speedup vs baseline: 1.3368x; 1.3368x over previous
#include <cuda_runtime.h>
#include <math.h>
#include <float.h>
#include <stdint.h>

// Problem constants (fixed by the dataset)
#define S_   7
#define B_   2
#define C_   80
#define NGT  32
#define BT_  8192
#define CELLF 90                    // B*5 + C
#define NCELLS (BT_ * S_ * S_)      // 401408
#define NBOX   (NCELLS * B_)        // 802816
#define NGTS   (BT_ * NGT)          // 262144

#define NTHR 128
#define NBLK 1024                   // fine-grained balance; 2 GTs per thread
#define NTOT (NBLK * NTHR)          // 131072 threads
#define GPT  (NGTS / NTOT)          // 2
#define NWARP (NTHR / 32)           // 4

typedef unsigned long long u64;

// Per-block partial sums: [coord, obj, posconf_sq, cls, npos, noobj_all]
__device__ double g_part[NBLK][6];
__device__ unsigned int g_count = 0;

__device__ __forceinline__ float sigmoidf_(float x) {
    return 1.0f / (1.0f + __expf(-x));
}

// ---- packed f32x2 helpers (sm_103a; ptxas won't auto-emit these) ----
__device__ __forceinline__ u64 mul2_(u64 a, u64 b) {
    u64 r; asm("mul.rn.f32x2 %0, %1, %2;" : "=l"(r) : "l"(a), "l"(b)); return r;
}
__device__ __forceinline__ u64 add2_(u64 a, u64 b) {
    u64 r; asm("add.rn.f32x2 %0, %1, %2;" : "=l"(r) : "l"(a), "l"(b)); return r;
}
__device__ __forceinline__ u64 fma2_(u64 a, u64 b, u64 c) {
    u64 r; asm("fma.rn.f32x2 %0, %1, %2, %3;" : "=l"(r) : "l"(a), "l"(b), "l"(c)); return r;
}
__device__ __forceinline__ u64 pack2_(float lo, float hi) {
    u64 r; asm("mov.b64 %0, {%1, %2};" : "=l"(r) : "f"(lo), "f"(hi)); return r;
}
__device__ __forceinline__ void unpack2_(u64 v, float& lo, float& hi) {
    asm("mov.b64 {%0, %1}, %2;" : "=f"(lo), "=f"(hi) : "l"(v));
}
__device__ __forceinline__ float ex2f_(float x) {
    float r; asm("ex2.approx.f32 %0, %1;" : "=f"(r) : "f"(x)); return r;
}
// packed exp: e = exp(x) elementwise on an f32x2 pair
__device__ __forceinline__ u64 exp2pair_(u64 x, u64 l2e2) {
    const u64 t = mul2_(x, l2e2);
    float a, bq; unpack2_(t, a, bq);
    return pack2_(ex2f_(a), ex2f_(bq));
}

__global__ void __launch_bounds__(NTHR, 8)
yolo_loss_fused(const float* __restrict__ preds,
                const float* __restrict__ gt_boxes,
                const int* __restrict__ gt_labels,
                const unsigned char* __restrict__ gt_valid,
                float* __restrict__ out)
{
    const int tid  = threadIdx.x;
    const int lane = tid & 31;
    const int wid  = tid >> 5;
    const int t0   = blockIdx.x * NTHR + tid;
    const unsigned FULL = 0xffffffffu;
    const u64 L2E2 = pack2_(1.4426950408889634f, 1.4426950408889634f);

    float coord = 0.f, obj = 0.f, posconf = 0.f, clsl = 0.f, npos = 0.f, noobj = 0.f;

    // ===== Phase 2 conf loads hoisted: independent MLP during gather latency =====
    {
        const float a0 = __ldg(preds + (size_t)t0 * CELLF + 4);
        const float b0 = __ldg(preds + (size_t)t0 * CELLF + 9);
        const float a1 = __ldg(preds + (size_t)(t0 + NTOT) * CELLF + 4);
        const float b1 = __ldg(preds + (size_t)(t0 + NTOT) * CELLF + 9);
        const float a2 = __ldg(preds + (size_t)(t0 + 2 * NTOT) * CELLF + 4);
        const float b2 = __ldg(preds + (size_t)(t0 + 2 * NTOT) * CELLF + 9);
        float a3 = 0.f, b3 = 0.f;
        const bool has4 = (t0 + 3 * NTOT) < NCELLS;
        if (has4) {
            a3 = __ldg(preds + (size_t)(t0 + 3 * NTOT) * CELLF + 4);
            b3 = __ldg(preds + (size_t)(t0 + 3 * NTOT) * CELLF + 9);
        }
        const float s0 = sigmoidf_(a0), s1 = sigmoidf_(b0);
        const float s2 = sigmoidf_(a1), s3 = sigmoidf_(b1);
        const float s4 = sigmoidf_(a2), s5 = sigmoidf_(b2);
        noobj = s0*s0 + s1*s1 + s2*s2 + s3*s3 + s4*s4 + s5*s5;
        if (has4) {
            const float s6 = sigmoidf_(a3), s7 = sigmoidf_(b3);
            noobj += s6*s6 + s7*s7;
        }
    }

    // ================= Phase 1: 2 GTs per thread, fully unrolled =================
    #pragma unroll
    for (int g = 0; g < GPT; g++) {
        const int t = t0 + g * NTOT;

        const float mval = (__ldg(gt_valid + t) != 0) ? 1.0f : 0.0f;
        const float4 gb  = __ldg((const float4*)gt_boxes + t);
        const int   label = __ldg(gt_labels + t);

        const float x1 = gb.x, y1 = gb.y, x2 = gb.z, y2 = gb.w;
        const float cx = (x1 + x2) * 0.5f;
        const float cy = (y1 + y2) * 0.5f;
        const float w  = fmaxf(x2 - x1, 1e-6f);
        const float h  = fmaxf(y2 - y1, 1e-6f);
        const int gi = min(max((int)floorf(cx * (float)S_), 0), S_ - 1);
        const int gj = min(max((int)floorf(cy * (float)S_), 0), S_ - 1);

        const int  b       = t >> 5;                       // t / NGT
        const int  cellIdx = b * (S_ * S_) + gj * S_ + gi;
        const float* cell  = preds + (size_t)cellIdx * CELLF;

        // label-logit gather (independent scalar load, overlaps everything)
        const float cl = __ldg(cell + 10 + label);

        // 16B-aligned vec4 view: off = 0 (even cell) or 2 floats (odd cell)
        const int   off  = (cellIdx & 1) << 1;             // 0 or 2
        const float msh  = (float)(off >> 1);              // 1.0 if shifted
        const float mns  = 1.0f - msh;                     // 1.0 if not shifted
        const float4* v4 = (const float4*)(cell - off);
        const ulonglong2* vu = (const ulonglong2*)(cell - off);
        const u64 MSH2 = pack2_(msh, msh);

        // ---- head: loaded positions 0..11 ----
        float p[12];
        {
            const float4 a  = __ldg(v4 + 0);
            const float4 bq = __ldg(v4 + 1);
            const float4 c  = __ldg(v4 + 2);
            p[0]=a.x;  p[1]=a.y;  p[2]=a.z;  p[3]=a.w;
            p[4]=bq.x; p[5]=bq.y; p[6]=bq.z; p[7]=bq.w;
            p[8]=c.x;  p[9]=c.y;  p[10]=c.z; p[11]=c.w;
        }
        float bx[10];
        #pragma unroll
        for (int j = 0; j < 10; j++) bx[j] = (off != 0) ? p[j + 2] : p[j];

        // off=0: positions 10,11 are class logits 10,11 (else box floats)
        const float e10 = __expf(p[10]);
        const float e11 = __expf(p[11]);
        float hs = mns * (e10 + e11);
        float hq = mns * (e10*e10 + e11*e11);

        // ---- body: positions 12..91 (vec 3..22), packed f32x2 accumulation ----
        u64 sA = 0ull, sB = 0ull, qA = 0ull, qB = 0ull;   // (0.0f,0.0f) packed
        #pragma unroll
        for (int ch = 0; ch < 4; ch++) {
            ulonglong2 u0 = __ldg(vu + 3 + ch*5 + 0);
            ulonglong2 u1 = __ldg(vu + 3 + ch*5 + 1);
            ulonglong2 u2 = __ldg(vu + 3 + ch*5 + 2);
            ulonglong2 u3 = __ldg(vu + 3 + ch*5 + 3);
            ulonglong2 u4 = __ldg(vu + 3 + ch*5 + 4);
            u64 lo[5] = {u0.x, u1.x, u2.x, u3.x, u4.x};
            u64 hi[5] = {u0.y, u1.y, u2.y, u3.y, u4.y};
            #pragma unroll
            for (int k = 0; k < 5; k++) {
                u64 eA = exp2pair_(lo[k], L2E2);
                u64 eB = exp2pair_(hi[k], L2E2);
                if (ch == 3 && k == 4) eB = mul2_(eB, MSH2);   // positions 90,91
                sA = add2_(sA, eA);  qA = fma2_(eA, eA, qA);
                sB = add2_(sB, eB);  qB = fma2_(eB, eB, qB);
            }
        }
        float sa0, sa1, sb0, sb1, qa0, qa1, qb0, qb1;
        unpack2_(sA, sa0, sa1); unpack2_(sB, sb0, sb1);
        unpack2_(qA, qa0, qa1); unpack2_(qB, qb0, qb1);
        const float s  = ((sa0 + sa1) + (sb0 + sb1)) + hs;
        const float sq = ((qa0 + qa1) + (qb0 + qb1)) + hq;

        const float el = __expf(cl);
        const float inv = 1.0f / s;
        const float cls_term = sq * inv * inv - 2.0f * el * inv + 1.0f;

        // ---- IoU over both candidate boxes ----
        const float area_g = (x2 - x1) * (y2 - y1);
        float iou[2], sxk[2], syk[2], twk[2], thk[2], tok[2];
        #pragma unroll
        for (int k = 0; k < 2; k++) {
            const float tx = bx[k*5+0], ty = bx[k*5+1];
            const float tw = bx[k*5+2], th = bx[k*5+3];
            const float sx = sigmoidf_(tx);
            const float sy = sigmoidf_(ty);
            const float pw = tw * tw, ph = th * th;
            const float px = (sx + (float)gi) * (1.0f / S_);
            const float py = (sy + (float)gj) * (1.0f / S_);
            const float px1 = px - 0.5f * pw, px2v = px + 0.5f * pw;
            const float py1 = py - 0.5f * ph, py2v = py + 0.5f * ph;
            const float iw = fmaxf(0.f, fminf(px2v, x2) - fmaxf(px1, x1));
            const float ih = fmaxf(0.f, fminf(py2v, y2) - fmaxf(py1, y1));
            const float inter = iw * ih;
            iou[k] = inter / (pw * ph + area_g - inter + 1e-6f);
            sxk[k] = sx; syk[k] = sy; twk[k] = tw; thk[k] = th; tok[k] = bx[k*5+4];
        }
        const int   best = (iou[1] > iou[0]) ? 1 : 0;
        const float iou_best = fmaxf(iou[0], iou[1]);

        const float so  = sigmoidf_(tok[best]);
        const float tgx = cx * (float)S_ - (float)gi;
        const float tgy = cy * (float)S_ - (float)gj;
        const float tgw = sqrtf(w), tgh = sqrtf(h);
        const float dx = sxk[best] - tgx, dy = syk[best] - tgy;
        const float dw = twk[best] - tgw, dh = thk[best] - tgh;
        const float dob = so - iou_best;

        coord   += mval * (dx*dx + dy*dy + dw*dw + dh*dh);
        obj     += mval * dob * dob;
        posconf += mval * so * so;
        npos    += mval;
        clsl    += mval * cls_term;
    }

    // ================= Block reduction -> g_part =================
    float vals[6] = {coord, obj, posconf, clsl, npos, noobj};
    #pragma unroll
    for (int j = 0; j < 6; j++) {
        #pragma unroll
        for (int o = 16; o; o >>= 1)
            vals[j] += __shfl_xor_sync(FULL, vals[j], o);
    }
    __shared__ double sh[NWARP][6];
    if (lane == 0) {
        #pragma unroll
        for (int j = 0; j < 6; j++) sh[wid][j] = (double)vals[j];
    }
    __syncthreads();
    if (tid < 6) {
        double acc = 0.0;
        #pragma unroll
        for (int wI = 0; wI < NWARP; wI++) acc += sh[wI][tid];
        g_part[blockIdx.x][tid] = acc;
    }

    // ================= Grid-wide finalize: last block reduces =================
    __shared__ bool is_last;
    __threadfence();
    if (tid == 0) {
        const unsigned prev = atomicAdd(&g_count, 1u);
        is_last = (prev == (unsigned)(NBLK - 1));
        if (is_last) g_count = 0u;          // reset for next graph replay
    }
    __syncthreads();
    if (!is_last) return;

    double a[6] = {0, 0, 0, 0, 0, 0};
    for (int bb = tid; bb < NBLK; bb += NTHR) {
        #pragma unroll
        for (int j = 0; j < 6; j++) a[j] += __ldcg(&g_part[bb][j]);
    }
    #pragma unroll
    for (int j = 0; j < 6; j++) {
        #pragma unroll
        for (int o = 16; o; o >>= 1)
            a[j] += __shfl_xor_sync(FULL, a[j], o);
    }
    __shared__ double shf[NWARP][6];
    if (lane == 0) {
        #pragma unroll
        for (int j = 0; j < 6; j++) shf[wid][j] = a[j];
    }
    __syncthreads();
    if (tid == 0) {
        double tt[6];
        #pragma unroll
        for (int j = 0; j < 6; j++) {
            tt[j] = 0.0;
            for (int wI = 0; wI < NWARP; wI++) tt[j] += shf[wI][j];
        }
        const double nposd = fmax(tt[4], 1.0);
        const double nneg  = fmax((double)NBOX - tt[4], 1.0);
        const double ncell = fmax(tt[4], 1.0);   // GT cells are distinct per batch item
        const double loss = 5.0 * tt[0] / nposd          // LC * coord
                          + tt[1] / nposd                // obj
                          + 0.5 * (tt[5] - tt[2]) / nneg // LN * noobj (all - positive)
                          + tt[3] / ncell;               // cls
        *out = (float)loss;
    }
}

extern "C" void kernel_launch(void* const* d_in, const int* in_sizes, int n_in,
                              void* d_out, int out_size)
{
    const float*         preds     = (const float*)d_in[0];
    const float*         gt_boxes  = (const float*)d_in[1];
    const int*           gt_labels = (const int*)d_in[2];
    const unsigned char* gt_valid  = (const unsigned char*)d_in[3];
    float* out = (float*)d_out;

    yolo_loss_fused<<<NBLK, NTHR>>>(preds, gt_boxes, gt_labels, gt_valid, out);
}